// round 10
// baseline (speedup 1.0000x reference)
#include <cuda_runtime.h>
#include <cuda_bf16.h>
#include <math.h>
#include <stdint.h>

// Problem constants
#define BB 16
#define PP 2048
#define DD 512
#define HH 8
#define CC 64
#define HD 64
#define MM (BB*PP)          // 32768
#define FFN_IN 1024
#define FFN_HID 4096

// ---------------- device scratch (no runtime allocation allowed) ----------
__device__ float g_q[(size_t)MM*DD];            // value projection (fp32)
__device__ float g_aff[(size_t)BB*HH*CC*PP];
__device__ float g_ac2p[(size_t)BB*HH*CC*PP];
__device__ float g_ap2c[(size_t)BB*HH*CC*PP];
__device__ float g_vcore[(size_t)BB*HH*CC*HD];
__device__ float g_ffnout[(size_t)MM*DD];

// bf16 split operands (hi/lo)
__device__ __align__(16) __nv_bfloat16 g_xh[(size_t)MM*DD];
__device__ __align__(16) __nv_bfloat16 g_xl[(size_t)MM*DD];
__device__ __align__(16) __nv_bfloat16 g_fh[(size_t)MM*FFN_IN];
__device__ __align__(16) __nv_bfloat16 g_fl[(size_t)MM*FFN_IN];
__device__ __align__(16) __nv_bfloat16 g_hidh[(size_t)MM*FFN_HID];
__device__ __align__(16) __nv_bfloat16 g_hidl[(size_t)MM*FFN_HID];
// weights transposed to [N][K] K-major, split hi/lo
__device__ __align__(16) __nv_bfloat16 g_wvh[(size_t)DD*DD];
__device__ __align__(16) __nv_bfloat16 g_wvl[(size_t)DD*DD];
__device__ __align__(16) __nv_bfloat16 g_w1h[(size_t)FFN_HID*FFN_IN];
__device__ __align__(16) __nv_bfloat16 g_w1l[(size_t)FFN_HID*FFN_IN];
__device__ __align__(16) __nv_bfloat16 g_w2h[(size_t)DD*FFN_HID];
__device__ __align__(16) __nv_bfloat16 g_w2l[(size_t)DD*FFN_HID];

// ---------------- helpers -------------------------------------------------
__device__ __forceinline__ uint32_t smem_u32(const void* p) {
    uint32_t a;
    asm("{ .reg .u64 t; cvta.to.shared.u64 t, %1; cvt.u32.u64 %0, t; }"
        : "=r"(a) : "l"(p));
    return a;
}
#define LDSM4(r0, r1, r2, r3, addr) \
    asm volatile("ldmatrix.sync.aligned.m8n8.x4.shared.b16 {%0,%1,%2,%3}, [%4];" \
        : "=r"(r0), "=r"(r1), "=r"(r2), "=r"(r3) : "r"(addr))
#define MMA16816(d, a, b) \
    asm volatile("mma.sync.aligned.m16n8k16.row.col.f32.bf16.bf16.f32 " \
        "{%0,%1,%2,%3},{%4,%5,%6,%7},{%8,%9},{%0,%1,%2,%3};" \
        : "+f"((d)[0]), "+f"((d)[1]), "+f"((d)[2]), "+f"((d)[3]) \
        : "r"((a)[0]), "r"((a)[1]), "r"((a)[2]), "r"((a)[3]), \
          "r"((b)[0]), "r"((b)[1]))

// GEMM tiling
#define GBM 128
#define GBN 128
#define GBK 32
#define SROW 40                  // padded row (80B): conflict-free ldmatrix
#define ARR_SZ (128*SROW)        // 5120 bf16 per operand tile
#define STG_SZ (4*ARR_SZ)        // Ah|Al|Bh|Bl per stage
#define SMEM_BYTES (2*STG_SZ*2)  // 81920 bytes

// ---------------------------------------------------------------------------
// mma.sync bf16x3-split GEMM: C(M x Nfull) = split(A) @ split(B)^T + epilogue
// A: [M][K] bf16 hi/lo (K-major), B: [Nfull][K] bf16 hi/lo (K-major)
// CTA 128x128x32, 8 warps (2x4), warp tile 64x32, double-buffered smem.
// 3 products: AhBh + AhBl + AlBh, fp32 accumulators.
// Grid: x = M-tile (fast) -> one wave shares one B strip (L2-resident).
// mode 0: Cf = D + bias ; mode 1: gelu(D+bias) -> Ch/Cl bf16 split
// mode 2: Cf = D + bias + Xres
// ---------------------------------------------------------------------------
__global__ __launch_bounds__(256) void mma_gemm(
    const __nv_bfloat16* __restrict__ Ah, const __nv_bfloat16* __restrict__ Al,
    const __nv_bfloat16* __restrict__ Bh, const __nv_bfloat16* __restrict__ Bl,
    const float* __restrict__ bias, const float* __restrict__ Xres,
    float* __restrict__ Cf, __nv_bfloat16* __restrict__ Ch,
    __nv_bfloat16* __restrict__ Cl,
    int K, int Nfull, int mode)
{
    extern __shared__ __align__(16) __nv_bfloat16 sm[];
    const uint32_t smb = smem_u32(sm);
    const int tid = threadIdx.x;
    const int wid = tid >> 5, lane = tid & 31;
    const int warp_m = wid >> 2, warp_n = wid & 3;   // 2 x 4
    const int bm = blockIdx.x * GBM;
    const int bn = blockIdx.y * GBN;

    float acc[4][4][4];
#pragma unroll
    for (int i = 0; i < 4; i++)
#pragma unroll
        for (int j = 0; j < 4; j++)
#pragma unroll
            for (int k = 0; k < 4; k++) acc[i][j][k] = 0.0f;

    const int nk = K / GBK;

    // chunk mapping: c in [0,512): row = c>>2, seg = c&3 (16B each); thread
    // handles c = tid and c = tid + 256 for each of the 4 operand tiles.
    auto load_regs = [&](int ks, uint4* pA, uint4* pAl, uint4* pB, uint4* pBl) {
        const int k0 = ks * GBK;
#pragma unroll
        for (int u = 0; u < 2; u++) {
            const int c = tid + u * 256;
            const int row = c >> 2, seg = c & 3;
            const size_t ga = (size_t)(bm + row) * K + k0 + seg * 8;
            const size_t gb = (size_t)(bn + row) * K + k0 + seg * 8;
            pA[u]  = *(const uint4*)(Ah + ga);
            pAl[u] = *(const uint4*)(Al + ga);
            pB[u]  = *(const uint4*)(Bh + gb);
            pBl[u] = *(const uint4*)(Bl + gb);
        }
    };
    auto store_smem = [&](int buf, const uint4* pA, const uint4* pAl,
                          const uint4* pB, const uint4* pBl) {
#pragma unroll
        for (int u = 0; u < 2; u++) {
            const int c = tid + u * 256;
            const int row = c >> 2, seg = c & 3;
            const int off = row * SROW + seg * 8;
            __nv_bfloat16* base = sm + buf * STG_SZ;
            *(uint4*)(base + 0*ARR_SZ + off) = pA[u];
            *(uint4*)(base + 1*ARR_SZ + off) = pAl[u];
            *(uint4*)(base + 2*ARR_SZ + off) = pB[u];
            *(uint4*)(base + 3*ARR_SZ + off) = pBl[u];
        }
    };

    {   // prologue
        uint4 a[2], al[2], b[2], bl[2];
        load_regs(0, a, al, b, bl);
        store_smem(0, a, al, b, bl);
    }
    __syncthreads();

    const int mat = lane >> 3, rsel = lane & 7;

    for (int s = 0; s < nk; s++) {
        const int cur = s & 1;
        uint4 pa[2], pal[2], pb[2], pbl[2];
        const bool more = (s + 1 < nk);
        if (more) load_regs(s + 1, pa, pal, pb, pbl);

        const uint32_t stg = smb + (uint32_t)(cur * STG_SZ) * 2;
#pragma unroll
        for (int ko = 0; ko < 2; ko++) {
            uint32_t ah[4][4], al_[4][4], bh[4][2], bl_[4][2];
            // A fragments (Ah, Al): 4 m-frags each
#pragma unroll
            for (int mi = 0; mi < 4; mi++) {
                const int m_off = warp_m*64 + mi*16 + (mat & 1)*8 + rsel;
                const int k_off = ko*16 + (mat >> 1)*8;
                const uint32_t adr = stg + (uint32_t)(m_off*SROW + k_off)*2;
                LDSM4(ah[mi][0], ah[mi][1], ah[mi][2], ah[mi][3], adr);
                LDSM4(al_[mi][0], al_[mi][1], al_[mi][2], al_[mi][3],
                      adr + ARR_SZ*2);
            }
            // B fragments (Bh, Bl): 2 x4 loads cover 4 n-frags each
#pragma unroll
            for (int nb = 0; nb < 2; nb++) {
                const int n_off = warp_n*32 + nb*16 + (mat >> 1)*8 + rsel;
                const int k_off = ko*16 + (mat & 1)*8;
                const uint32_t adr = stg + (uint32_t)(2*ARR_SZ + n_off*SROW + k_off)*2;
                uint32_t t0, t1, t2, t3;
                LDSM4(t0, t1, t2, t3, adr);
                bh[2*nb][0] = t0; bh[2*nb][1] = t1;
                bh[2*nb+1][0] = t2; bh[2*nb+1][1] = t3;
                LDSM4(t0, t1, t2, t3, adr + ARR_SZ*2);
                bl_[2*nb][0] = t0; bl_[2*nb][1] = t1;
                bl_[2*nb+1][0] = t2; bl_[2*nb+1][1] = t3;
            }
            // 3-product MMA
#pragma unroll
            for (int mi = 0; mi < 4; mi++)
#pragma unroll
                for (int ni = 0; ni < 4; ni++) {
                    MMA16816(acc[mi][ni], ah[mi], bh[ni]);
                    MMA16816(acc[mi][ni], ah[mi], bl_[ni]);
                    MMA16816(acc[mi][ni], al_[mi], bh[ni]);
                }
        }

        if (more) store_smem(cur ^ 1, pa, pal, pb, pbl);
        __syncthreads();
    }

    // ---- epilogue ----
    const int gr = lane >> 2;          // 0..7
    const int gc = (lane & 3) * 2;     // 0,2,4,6
#pragma unroll
    for (int mi = 0; mi < 4; mi++) {
        const int r0 = bm + warp_m*64 + mi*16 + gr;
        const int r1 = r0 + 8;
#pragma unroll
        for (int ni = 0; ni < 4; ni++) {
            const int col = bn + warp_n*32 + ni*8 + gc;
            const float2 b2 = *(const float2*)(bias + col);
            float c00 = acc[mi][ni][0] + b2.x;
            float c01 = acc[mi][ni][1] + b2.y;
            float c10 = acc[mi][ni][2] + b2.x;
            float c11 = acc[mi][ni][3] + b2.y;
            if (mode == 0) {
                *(float2*)(Cf + (size_t)r0 * Nfull + col) = make_float2(c00, c01);
                *(float2*)(Cf + (size_t)r1 * Nfull + col) = make_float2(c10, c11);
            } else if (mode == 1) {
                c00 = 0.5f*c00*(1.0f + erff(c00*0.70710678118654752f));
                c01 = 0.5f*c01*(1.0f + erff(c01*0.70710678118654752f));
                c10 = 0.5f*c10*(1.0f + erff(c10*0.70710678118654752f));
                c11 = 0.5f*c11*(1.0f + erff(c11*0.70710678118654752f));
                __nv_bfloat16 h00 = __float2bfloat16(c00);
                __nv_bfloat16 h01 = __float2bfloat16(c01);
                __nv_bfloat16 h10 = __float2bfloat16(c10);
                __nv_bfloat16 h11 = __float2bfloat16(c11);
                __nv_bfloat162 ph0; ph0.x = h00; ph0.y = h01;
                __nv_bfloat162 ph1; ph1.x = h10; ph1.y = h11;
                __nv_bfloat162 pl0;
                pl0.x = __float2bfloat16(c00 - __bfloat162float(h00));
                pl0.y = __float2bfloat16(c01 - __bfloat162float(h01));
                __nv_bfloat162 pl1;
                pl1.x = __float2bfloat16(c10 - __bfloat162float(h10));
                pl1.y = __float2bfloat16(c11 - __bfloat162float(h11));
                *(__nv_bfloat162*)(Ch + (size_t)r0 * Nfull + col) = ph0;
                *(__nv_bfloat162*)(Ch + (size_t)r1 * Nfull + col) = ph1;
                *(__nv_bfloat162*)(Cl + (size_t)r0 * Nfull + col) = pl0;
                *(__nv_bfloat162*)(Cl + (size_t)r1 * Nfull + col) = pl1;
            } else {
                const float2 x0 = *(const float2*)(Xres + (size_t)r0 * 512 + col);
                const float2 x1 = *(const float2*)(Xres + (size_t)r1 * 512 + col);
                *(float2*)(Cf + (size_t)r0 * Nfull + col) =
                    make_float2(c00 + x0.x, c01 + x0.y);
                *(float2*)(Cf + (size_t)r1 * Nfull + col) =
                    make_float2(c10 + x1.x, c11 + x1.y);
            }
        }
    }
}

// ---------------------------------------------------------------------------
// pre-pass: elementwise fp32 -> bf16 hi/lo split (float4 granularity)
// ---------------------------------------------------------------------------
__global__ void split_kernel(const float* __restrict__ s,
                             __nv_bfloat16* __restrict__ h,
                             __nv_bfloat16* __restrict__ l, int n4)
{
    int i = blockIdx.x * blockDim.x + threadIdx.x;
    if (i >= n4) return;
    const float4 v = ((const float4*)s)[i];
    float a[4] = {v.x, v.y, v.z, v.w};
    __nv_bfloat16 hh[4], ll[4];
#pragma unroll
    for (int j = 0; j < 4; j++) {
        hh[j] = __float2bfloat16(a[j]);
        ll[j] = __float2bfloat16(a[j] - __bfloat162float(hh[j]));
    }
    __nv_bfloat162 p0; p0.x = hh[0]; p0.y = hh[1];
    __nv_bfloat162 p1; p1.x = hh[2]; p1.y = hh[3];
    __nv_bfloat162 q0; q0.x = ll[0]; q0.y = ll[1];
    __nv_bfloat162 q1; q1.x = ll[2]; q1.y = ll[3];
    ((__nv_bfloat162*)h)[i*2]   = p0;
    ((__nv_bfloat162*)h)[i*2+1] = p1;
    ((__nv_bfloat162*)l)[i*2]   = q0;
    ((__nv_bfloat162*)l)[i*2+1] = q1;
}

// pre-pass: W [K][N] fp32 -> Wh/Wl [N][K] bf16 (transpose + split)
__global__ void wsplit_kernel(const float* __restrict__ W,
                              __nv_bfloat16* __restrict__ Wh,
                              __nv_bfloat16* __restrict__ Wl, int K, int N)
{
    __shared__ float s[32][33];
    const int k0 = blockIdx.y * 32, n0 = blockIdx.x * 32;
    const int tx = threadIdx.x, ty = threadIdx.y;   // 32 x 8
#pragma unroll
    for (int i = 0; i < 4; i++)
        s[ty + 8*i][tx] = W[(size_t)(k0 + ty + 8*i) * N + n0 + tx];
    __syncthreads();
#pragma unroll
    for (int i = 0; i < 4; i++) {
        const float v = s[tx][ty + 8*i];
        const __nv_bfloat16 h = __float2bfloat16(v);
        const __nv_bfloat16 l = __float2bfloat16(v - __bfloat162float(h));
        const size_t o = (size_t)(n0 + ty + 8*i) * K + k0 + tx;
        Wh[o] = h;
        Wl[o] = l;
    }
}

// ---------------------------------------------------------------------------
// routing kernels (SIMT fp32 — small fraction of runtime)
// ---------------------------------------------------------------------------
__global__ __launch_bounds__(256) void aff_kernel(
    const float* __restrict__ q, const float* __restrict__ cores,
    float* __restrict__ aff)
{
    const int bh = blockIdx.y;
    const int b = bh >> 3, h = bh & 7;
    const int p0 = blockIdx.x * 64;
    __shared__ float cs[64][64];
    __shared__ float qs[64][65];
    const int tid = threadIdx.x;
    for (int idx = tid; idx < 4096; idx += 256) {
        int c = idx >> 6, d = idx & 63;
        cs[c][d] = cores[((size_t)h*64 + c)*64 + d];
    }
    for (int idx = tid; idx < 4096; idx += 256) {
        int p = idx >> 6, d = idx & 63;
        qs[p][d] = q[((size_t)(b*PP + p0 + p))*DD + h*64 + d];
    }
    __syncthreads();
    const int tp = tid & 31;
    const int tc = tid >> 5;
    float acc[2][8];
#pragma unroll
    for (int pp = 0; pp < 2; pp++)
#pragma unroll
        for (int cc = 0; cc < 8; cc++) acc[pp][cc] = 0.0f;
    for (int d = 0; d < 64; d++) {
        float qv0 = qs[tp][d];
        float qv1 = qs[tp + 32][d];
        float cv[8];
#pragma unroll
        for (int cc = 0; cc < 8; cc++) cv[cc] = cs[tc + 8*cc][d];
#pragma unroll
        for (int cc = 0; cc < 8; cc++) {
            acc[0][cc] += qv0 * cv[cc];
            acc[1][cc] += qv1 * cv[cc];
        }
    }
#pragma unroll
    for (int pp = 0; pp < 2; pp++)
#pragma unroll
        for (int cc = 0; cc < 8; cc++)
            aff[((size_t)bh*64 + tc + 8*cc)*PP + p0 + tp + 32*pp] = acc[pp][cc] * 0.125f;
}

__global__ __launch_bounds__(256) void softmax_p_kernel(
    const float* __restrict__ aff, float* __restrict__ out)
{
    const int row = blockIdx.x;
    const float* a = aff + (size_t)row * PP;
    const int tid = threadIdx.x;
    __shared__ float sm[256];
    float v[8];
    float m = -1e30f;
#pragma unroll
    for (int i = 0; i < 8; i++) { v[i] = a[tid + 256*i]; m = fmaxf(m, v[i]); }
    sm[tid] = m; __syncthreads();
    for (int s = 128; s > 0; s >>= 1) {
        if (tid < s) sm[tid] = fmaxf(sm[tid], sm[tid + s]);
        __syncthreads();
    }
    m = sm[0];
    __syncthreads();
    float s = 0.0f;
#pragma unroll
    for (int i = 0; i < 8; i++) { v[i] = expf(v[i] - m); s += v[i]; }
    sm[tid] = s; __syncthreads();
    for (int s2 = 128; s2 > 0; s2 >>= 1) {
        if (tid < s2) sm[tid] += sm[tid + s2];
        __syncthreads();
    }
    const float inv = 1.0f / sm[0];
    float* o = out + (size_t)row * PP;
#pragma unroll
    for (int i = 0; i < 8; i++) o[tid + 256*i] = v[i] * inv;
}

__global__ __launch_bounds__(256) void softmax_c_kernel(
    const float* __restrict__ aff, float* __restrict__ out)
{
    const int bh = blockIdx.x;
    const int p0 = blockIdx.y * 64;
    __shared__ float t[64][65];
    __shared__ float red[4][64];
    const int tid = threadIdx.x;
    for (int idx = tid; idx < 4096; idx += 256) {
        int c = idx >> 6, p = idx & 63;
        t[c][p] = aff[((size_t)bh*64 + c)*PP + p0 + p];
    }
    __syncthreads();
    const int p = tid & 63;
    const int g = tid >> 6;
    float m = -1e30f;
    for (int c = g*16; c < g*16 + 16; c++) m = fmaxf(m, t[c][p]);
    red[g][p] = m; __syncthreads();
    const float mm = fmaxf(fmaxf(red[0][p], red[1][p]), fmaxf(red[2][p], red[3][p]));
    __syncthreads();
    float s = 0.0f;
    for (int c = g*16; c < g*16 + 16; c++) {
        const float e = expf(t[c][p] - mm);
        t[c][p] = e;
        s += e;
    }
    red[g][p] = s; __syncthreads();
    const float ss = red[0][p] + red[1][p] + red[2][p] + red[3][p];
    const float inv = 1.0f / ss;
    for (int c = g*16; c < g*16 + 16; c++)
        out[((size_t)bh*64 + c)*PP + p0 + p] = t[c][p] * inv;
}

__global__ __launch_bounds__(256) void vcore_kernel(
    const float* __restrict__ x, const float* __restrict__ ac2p,
    float* __restrict__ vcore)
{
    const int bh = blockIdx.x;
    const int b = bh >> 3, h = bh & 7;
    __shared__ float a_s[64][64];
    __shared__ float v_s[64][64];
    const int tid = threadIdx.x;
    const int tj = tid & 15;
    const int ti = tid >> 4;
    float acc[4][4];
#pragma unroll
    for (int i = 0; i < 4; i++)
#pragma unroll
        for (int j = 0; j < 4; j++) acc[i][j] = 0.0f;
    for (int p0 = 0; p0 < PP; p0 += 64) {
        for (int idx = tid; idx < 4096; idx += 256) {
            int c = idx >> 6, p = idx & 63;
            a_s[c][p] = ac2p[((size_t)bh*64 + c)*PP + p0 + p];
        }
        for (int idx = tid; idx < 4096; idx += 256) {
            int p = idx >> 6, d = idx & 63;
            v_s[p][d] = x[((size_t)(b*PP + p0 + p))*DD + h*64 + d];
        }
        __syncthreads();
        for (int p = 0; p < 64; p++) {
            float av[4], vv[4];
#pragma unroll
            for (int i = 0; i < 4; i++) av[i] = a_s[ti + 16*i][p];
#pragma unroll
            for (int j = 0; j < 4; j++) vv[j] = v_s[p][tj + 16*j];
#pragma unroll
            for (int i = 0; i < 4; i++)
#pragma unroll
                for (int j = 0; j < 4; j++) acc[i][j] += av[i] * vv[j];
        }
        __syncthreads();
    }
#pragma unroll
    for (int i = 0; i < 4; i++)
#pragma unroll
        for (int j = 0; j < 4; j++)
            vcore[((size_t)bh*64 + ti + 16*i)*64 + tj + 16*j] = acc[i][j];
}

// FUSED: v_patch + ffn-input concat + bf16 hi/lo split.
__global__ __launch_bounds__(256) void vpatch_ffnin_kernel(
    const float* __restrict__ vcore, const float* __restrict__ ap2c,
    const float* __restrict__ X,
    __nv_bfloat16* __restrict__ fh, __nv_bfloat16* __restrict__ fl)
{
    const int bh = blockIdx.x;
    const int b = bh >> 3, h = bh & 7;
    const int p0 = blockIdx.y * 64;
    __shared__ float vc[64][64];
    __shared__ float a_s[64][64];
    const int tid = threadIdx.x;
    for (int idx = tid; idx < 4096; idx += 256) {
        int c = idx >> 6, d = idx & 63;
        vc[c][d] = vcore[((size_t)bh*64 + c)*64 + d];
    }
    for (int idx = tid; idx < 4096; idx += 256) {
        int c = idx >> 6, p = idx & 63;
        a_s[c][p] = ap2c[((size_t)bh*64 + c)*PP + p0 + p];
    }
    __syncthreads();
    const int tj = tid & 15;
    const int ti = tid >> 4;
    float acc[4][4];
#pragma unroll
    for (int i = 0; i < 4; i++)
#pragma unroll
        for (int j = 0; j < 4; j++) acc[i][j] = 0.0f;
    for (int c = 0; c < 64; c++) {
        float av[4], vv[4];
#pragma unroll
        for (int i = 0; i < 4; i++) av[i] = a_s[c][ti + 16*i];
#pragma unroll
        for (int j = 0; j < 4; j++) vv[j] = vc[c][tj + 16*j];
#pragma unroll
        for (int i = 0; i < 4; i++)
#pragma unroll
            for (int j = 0; j < 4; j++) acc[i][j] += av[i] * vv[j];
    }
#pragma unroll
    for (int i = 0; i < 4; i++) {
        const size_t m = (size_t)(b*PP + p0 + ti + 16*i);
#pragma unroll
        for (int j = 0; j < 4; j++) {
            const int col = h*64 + tj + 16*j;
            const float v = acc[i][j];
            const float d1 = X[m*DD + col] - v;
            const __nv_bfloat16 h1 = __float2bfloat16(d1);
            fh[m*FFN_IN + col] = h1;
            fl[m*FFN_IN + col] = __float2bfloat16(d1 - __bfloat162float(h1));
            const __nv_bfloat16 h2 = __float2bfloat16(v);
            fh[m*FFN_IN + 512 + col] = h2;
            fl[m*FFN_IN + 512 + col] = __float2bfloat16(v - __bfloat162float(h2));
        }
    }
}

// LayerNorm over last dim (512). 256 threads/row; warp-shuffle reduction.
__global__ __launch_bounds__(256) void ln_kernel(
    const float* __restrict__ in, const float* __restrict__ gamma,
    const float* __restrict__ beta, float* __restrict__ out)
{
    const int row = blockIdx.x;
    const float* r = in + (size_t)row * DD;
    const int tid = threadIdx.x;
    const int wid = tid >> 5, lid = tid & 31;
    __shared__ float wsum[8], wsq[8];

    const float x0 = r[tid], x1 = r[tid + 256];
    float s  = x0 + x1;
    float sq = x0*x0 + x1*x1;
#pragma unroll
    for (int o = 16; o > 0; o >>= 1) {
        s  += __shfl_xor_sync(0xFFFFFFFFu, s,  o);
        sq += __shfl_xor_sync(0xFFFFFFFFu, sq, o);
    }
    if (lid == 0) { wsum[wid] = s; wsq[wid] = sq; }
    __syncthreads();
    float ts = wsum[lid & 7], tq = wsq[lid & 7];
#pragma unroll
    for (int o = 4; o > 0; o >>= 1) {
        ts += __shfl_xor_sync(0xFFFFFFFFu, ts, o);
        tq += __shfl_xor_sync(0xFFFFFFFFu, tq, o);
    }
    ts = __shfl_sync(0xFFFFFFFFu, ts, 0);
    tq = __shfl_sync(0xFFFFFFFFu, tq, 0);

    const float mu  = ts * (1.0f / 512.0f);
    const float var = tq * (1.0f / 512.0f) - mu*mu;
    const float inv = rsqrtf(var + 1e-5f);

    float* o = out + (size_t)row * DD;
    o[tid]       = (x0 - mu) * inv * gamma[tid]       + beta[tid];
    o[tid + 256] = (x1 - mu) * inv * gamma[tid + 256] + beta[tid + 256];
}

// ---------------------------------------------------------------------------
extern "C" void kernel_launch(void* const* d_in, const int* in_sizes, int n_in,
                              void* d_out, int out_size)
{
    const float* input = (const float*)d_in[0];
    const float* cores = (const float*)d_in[1];
    const float* Wv    = (const float*)d_in[2];
    const float* bv    = (const float*)d_in[3];
    const float* W1    = (const float*)d_in[4];
    const float* b1    = (const float*)d_in[5];
    const float* W2    = (const float*)d_in[6];
    const float* b2    = (const float*)d_in[7];
    const float* gamma = (const float*)d_in[8];
    const float* beta  = (const float*)d_in[9];
    float* out = (float*)d_out;

    float *q, *aff, *ac2p, *ap2c, *vcore, *ffnout;
    cudaGetSymbolAddress((void**)&q,      g_q);
    cudaGetSymbolAddress((void**)&aff,    g_aff);
    cudaGetSymbolAddress((void**)&ac2p,   g_ac2p);
    cudaGetSymbolAddress((void**)&ap2c,   g_ap2c);
    cudaGetSymbolAddress((void**)&vcore,  g_vcore);
    cudaGetSymbolAddress((void**)&ffnout, g_ffnout);
    __nv_bfloat16 *xh, *xl, *fh, *fl, *hh, *hl, *wvh, *wvl, *w1h, *w1l, *w2h, *w2l;
    cudaGetSymbolAddress((void**)&xh,  g_xh);
    cudaGetSymbolAddress((void**)&xl,  g_xl);
    cudaGetSymbolAddress((void**)&fh,  g_fh);
    cudaGetSymbolAddress((void**)&fl,  g_fl);
    cudaGetSymbolAddress((void**)&hh,  g_hidh);
    cudaGetSymbolAddress((void**)&hl,  g_hidl);
    cudaGetSymbolAddress((void**)&wvh, g_wvh);
    cudaGetSymbolAddress((void**)&wvl, g_wvl);
    cudaGetSymbolAddress((void**)&w1h, g_w1h);
    cudaGetSymbolAddress((void**)&w1l, g_w1l);
    cudaGetSymbolAddress((void**)&w2h, g_w2h);
    cudaGetSymbolAddress((void**)&w2l, g_w2l);

    cudaFuncSetAttribute(mma_gemm, cudaFuncAttributeMaxDynamicSharedMemorySize,
                         SMEM_BYTES);

    // --- pre-passes: operand splits ---
    split_kernel<<<(MM*DD/4 + 255)/256, 256>>>(input, xh, xl, MM*DD/4);
    wsplit_kernel<<<dim3(DD/32, DD/32), dim3(32,8)>>>(Wv, wvh, wvl, DD, DD);
    wsplit_kernel<<<dim3(FFN_HID/32, FFN_IN/32), dim3(32,8)>>>(W1, w1h, w1l, FFN_IN, FFN_HID);
    wsplit_kernel<<<dim3(DD/32, FFN_HID/32), dim3(32,8)>>>(W2, w2h, w2l, FFN_HID, DD);

    // --- 1) value projection: q = X @ Wv + bv (fp32 out) ---
    mma_gemm<<<dim3(MM/GBM, DD/GBN), 256, SMEM_BYTES>>>(
        xh, xl, wvh, wvl, bv, nullptr, q, nullptr, nullptr, DD, DD, 0);

    // --- 2-5) routing ---
    aff_kernel<<<dim3(PP/64, BB*HH), 256>>>(q, cores, aff);
    softmax_p_kernel<<<BB*HH*CC, 256>>>(aff, ac2p);
    softmax_c_kernel<<<dim3(BB*HH, PP/64), 256>>>(aff, ap2c);
    vcore_kernel<<<BB*HH, 256>>>(input, ac2p, vcore);

    // --- 6) fused v_patch + FFN-input concat/split ---
    vpatch_ffnin_kernel<<<dim3(BB*HH, PP/64), 256>>>(vcore, ap2c, input, fh, fl);

    // --- 7) FFN layer 1 + exact GELU -> hid (bf16 split) ---
    mma_gemm<<<dim3(MM/GBM, FFN_HID/GBN), 256, SMEM_BYTES>>>(
        fh, fl, w1h, w1l, b1, nullptr, nullptr, hh, hl, FFN_IN, FFN_HID, 1);

    // --- 8) FFN layer 2 + residual -> ffnout (fp32) ---
    mma_gemm<<<dim3(MM/GBM, DD/GBN), 256, SMEM_BYTES>>>(
        hh, hl, w2h, w2l, b2, input, ffnout, nullptr, nullptr, FFN_HID, DD, 2);

    // --- 9) LayerNorm -> output ---
    ln_kernel<<<MM, 256>>>(ffnout, gamma, beta, out);
}

// round 17
// speedup vs baseline: 1.2194x; 1.2194x over previous
#include <cuda_runtime.h>
#include <cuda_bf16.h>
#include <math.h>
#include <stdint.h>

// Problem constants
#define BB 16
#define PP 2048
#define DD 512
#define HH 8
#define CC 64
#define HD 64
#define MM (BB*PP)          // 32768
#define FFN_IN 1024
#define FFN_HID 4096

// ---------------- device scratch (no runtime allocation allowed) ----------
__device__ float g_q[(size_t)MM*DD];            // value projection (fp32)
__device__ float g_aff[(size_t)BB*HH*CC*PP];
__device__ float g_ac2p[(size_t)BB*HH*CC*PP];
__device__ float g_ap2c[(size_t)BB*HH*CC*PP];
__device__ float g_vcore[(size_t)BB*HH*CC*HD];
__device__ float g_ffnout[(size_t)MM*DD];

// bf16 split operands (hi/lo)
__device__ __align__(16) __nv_bfloat16 g_xh[(size_t)MM*DD];
__device__ __align__(16) __nv_bfloat16 g_xl[(size_t)MM*DD];
__device__ __align__(16) __nv_bfloat16 g_fh[(size_t)MM*FFN_IN];
__device__ __align__(16) __nv_bfloat16 g_fl[(size_t)MM*FFN_IN];
__device__ __align__(16) __nv_bfloat16 g_hidh[(size_t)MM*FFN_HID];
__device__ __align__(16) __nv_bfloat16 g_hidl[(size_t)MM*FFN_HID];
// weights transposed to [N][K] K-major, split hi/lo
__device__ __align__(16) __nv_bfloat16 g_wvh[(size_t)DD*DD];
__device__ __align__(16) __nv_bfloat16 g_wvl[(size_t)DD*DD];
__device__ __align__(16) __nv_bfloat16 g_w1h[(size_t)FFN_HID*FFN_IN];
__device__ __align__(16) __nv_bfloat16 g_w1l[(size_t)FFN_HID*FFN_IN];
__device__ __align__(16) __nv_bfloat16 g_w2h[(size_t)DD*FFN_HID];
__device__ __align__(16) __nv_bfloat16 g_w2l[(size_t)DD*FFN_HID];

// ---------------- helpers -------------------------------------------------
__device__ __forceinline__ uint32_t smem_u32(const void* p) {
    uint32_t a;
    asm("{ .reg .u64 t; cvta.to.shared.u64 t, %1; cvt.u32.u64 %0, t; }"
        : "=r"(a) : "l"(p));
    return a;
}
#define LDSM4(r0, r1, r2, r3, addr) \
    asm volatile("ldmatrix.sync.aligned.m8n8.x4.shared.b16 {%0,%1,%2,%3}, [%4];" \
        : "=r"(r0), "=r"(r1), "=r"(r2), "=r"(r3) : "r"(addr))
#define MMA16816(d, a, b) \
    asm volatile("mma.sync.aligned.m16n8k16.row.col.f32.bf16.bf16.f32 " \
        "{%0,%1,%2,%3},{%4,%5,%6,%7},{%8,%9},{%0,%1,%2,%3};" \
        : "+f"((d)[0]), "+f"((d)[1]), "+f"((d)[2]), "+f"((d)[3]) \
        : "r"((a)[0]), "r"((a)[1]), "r"((a)[2]), "r"((a)[3]), \
          "r"((b)[0]), "r"((b)[1]))
#define CP_ASYNC16(saddr, gptr) \
    asm volatile("cp.async.cg.shared.global [%0], [%1], 16;" \
        :: "r"(saddr), "l"(gptr))
#define CP_COMMIT() asm volatile("cp.async.commit_group;" ::: "memory")
#define CP_WAIT0()  asm volatile("cp.async.wait_group 0;" ::: "memory")

// GEMM tiling
#define GBM 128
#define GBN 128
#define GBK 32
#define SROW 40                  // padded row (80B): conflict-free ldmatrix
#define ARR_SZ (128*SROW)        // 5120 bf16 per operand tile
#define STG_SZ (4*ARR_SZ)        // Ah|Al|Bh|Bl per stage
#define SMEM_BYTES (2*STG_SZ*2)  // 81920 bytes

// ---------------------------------------------------------------------------
// mma.sync bf16x3-split GEMM: C(M x Nfull) = split(A) @ split(B)^T + epilogue
// A: [M][K] bf16 hi/lo (K-major), B: [Nfull][K] bf16 hi/lo (K-major)
// CTA 128x128x32, 8 warps (2x4), warp tile 64x32, cp.async double buffer.
// 3 products: AhBh + AhBl + AlBh, fp32 accumulators.
// Grid: x = N-tile (fast), y = M-tile -> one wave covers all N-tiles and
// shares each A tile via L2; weight matrix B stays L2-resident.
// 2 CTAs/SM target (regs<=128 via launch_bounds; smem 2x80KB).
// mode 0: Cf = D + bias ; mode 1: gelu(D+bias) -> Ch/Cl bf16 split
// mode 2: Cf = D + bias + Xres
// ---------------------------------------------------------------------------
__global__ __launch_bounds__(256, 2) void mma_gemm(
    const __nv_bfloat16* __restrict__ Ah, const __nv_bfloat16* __restrict__ Al,
    const __nv_bfloat16* __restrict__ Bh, const __nv_bfloat16* __restrict__ Bl,
    const float* __restrict__ bias, const float* __restrict__ Xres,
    float* __restrict__ Cf, __nv_bfloat16* __restrict__ Ch,
    __nv_bfloat16* __restrict__ Cl,
    int K, int Nfull, int mode)
{
    extern __shared__ __align__(16) __nv_bfloat16 sm[];
    const uint32_t smb = smem_u32(sm);
    const int tid = threadIdx.x;
    const int wid = tid >> 5, lane = tid & 31;
    const int warp_m = wid >> 2, warp_n = wid & 3;   // 2 x 4
    const int bm = blockIdx.y * GBM;
    const int bn = blockIdx.x * GBN;

    float acc[4][4][4];
#pragma unroll
    for (int i = 0; i < 4; i++)
#pragma unroll
        for (int j = 0; j < 4; j++)
#pragma unroll
            for (int k = 0; k < 4; k++) acc[i][j][k] = 0.0f;

    const int nk = K / GBK;

    // async copy of one k-stage into smem buffer `buf`
    auto cp_stage = [&](int buf, int ks) {
        const int k0 = ks * GBK;
        const uint32_t base = smb + (uint32_t)(buf * STG_SZ) * 2;
#pragma unroll
        for (int u = 0; u < 2; u++) {
            const int c = tid + u * 256;
            const int row = c >> 2, seg = c & 3;
            const uint32_t off = (uint32_t)(row * SROW + seg * 8) * 2;
            const size_t ga = (size_t)(bm + row) * K + k0 + seg * 8;
            const size_t gb = (size_t)(bn + row) * K + k0 + seg * 8;
            CP_ASYNC16(base + 0*ARR_SZ*2 + off, Ah + ga);
            CP_ASYNC16(base + 1*ARR_SZ*2 + off, Al + ga);
            CP_ASYNC16(base + 2*ARR_SZ*2 + off, Bh + gb);
            CP_ASYNC16(base + 3*ARR_SZ*2 + off, Bl + gb);
        }
    };

    cp_stage(0, 0);
    CP_COMMIT();
    CP_WAIT0();
    __syncthreads();

    const int mat = lane >> 3, rsel = lane & 7;

    for (int s = 0; s < nk; s++) {
        const int cur = s & 1;
        const bool more = (s + 1 < nk);
        if (more) { cp_stage(cur ^ 1, s + 1); CP_COMMIT(); }

        const uint32_t stg = smb + (uint32_t)(cur * STG_SZ) * 2;
#pragma unroll
        for (int ko = 0; ko < 2; ko++) {
            uint32_t ah[4][4], al_[4][4], bh[4][2], bl_[4][2];
            // A fragments (Ah, Al): 4 m-frags each
#pragma unroll
            for (int mi = 0; mi < 4; mi++) {
                const int m_off = warp_m*64 + mi*16 + (mat & 1)*8 + rsel;
                const int k_off = ko*16 + (mat >> 1)*8;
                const uint32_t adr = stg + (uint32_t)(m_off*SROW + k_off)*2;
                LDSM4(ah[mi][0], ah[mi][1], ah[mi][2], ah[mi][3], adr);
                LDSM4(al_[mi][0], al_[mi][1], al_[mi][2], al_[mi][3],
                      adr + ARR_SZ*2);
            }
            // B fragments (Bh, Bl): 2 x4 loads cover 4 n-frags each
#pragma unroll
            for (int nb = 0; nb < 2; nb++) {
                const int n_off = warp_n*32 + nb*16 + (mat >> 1)*8 + rsel;
                const int k_off = ko*16 + (mat & 1)*8;
                const uint32_t adr = stg + (uint32_t)(2*ARR_SZ + n_off*SROW + k_off)*2;
                uint32_t t0, t1, t2, t3;
                LDSM4(t0, t1, t2, t3, adr);
                bh[2*nb][0] = t0; bh[2*nb][1] = t1;
                bh[2*nb+1][0] = t2; bh[2*nb+1][1] = t3;
                LDSM4(t0, t1, t2, t3, adr + ARR_SZ*2);
                bl_[2*nb][0] = t0; bl_[2*nb][1] = t1;
                bl_[2*nb+1][0] = t2; bl_[2*nb+1][1] = t3;
            }
            // 3-product MMA
#pragma unroll
            for (int mi = 0; mi < 4; mi++)
#pragma unroll
                for (int ni = 0; ni < 4; ni++) {
                    MMA16816(acc[mi][ni], ah[mi], bh[ni]);
                    MMA16816(acc[mi][ni], ah[mi], bl_[ni]);
                    MMA16816(acc[mi][ni], al_[mi], bh[ni]);
                }
        }

        if (more) CP_WAIT0();
        __syncthreads();
    }

    // ---- epilogue ----
    const int gr = lane >> 2;          // 0..7
    const int gc = (lane & 3) * 2;     // 0,2,4,6
#pragma unroll
    for (int mi = 0; mi < 4; mi++) {
        const int r0 = bm + warp_m*64 + mi*16 + gr;
        const int r1 = r0 + 8;
#pragma unroll
        for (int ni = 0; ni < 4; ni++) {
            const int col = bn + warp_n*32 + ni*8 + gc;
            const float2 b2 = *(const float2*)(bias + col);
            float c00 = acc[mi][ni][0] + b2.x;
            float c01 = acc[mi][ni][1] + b2.y;
            float c10 = acc[mi][ni][2] + b2.x;
            float c11 = acc[mi][ni][3] + b2.y;
            if (mode == 0) {
                *(float2*)(Cf + (size_t)r0 * Nfull + col) = make_float2(c00, c01);
                *(float2*)(Cf + (size_t)r1 * Nfull + col) = make_float2(c10, c11);
            } else if (mode == 1) {
                c00 = 0.5f*c00*(1.0f + erff(c00*0.70710678118654752f));
                c01 = 0.5f*c01*(1.0f + erff(c01*0.70710678118654752f));
                c10 = 0.5f*c10*(1.0f + erff(c10*0.70710678118654752f));
                c11 = 0.5f*c11*(1.0f + erff(c11*0.70710678118654752f));
                __nv_bfloat16 h00 = __float2bfloat16(c00);
                __nv_bfloat16 h01 = __float2bfloat16(c01);
                __nv_bfloat16 h10 = __float2bfloat16(c10);
                __nv_bfloat16 h11 = __float2bfloat16(c11);
                __nv_bfloat162 ph0; ph0.x = h00; ph0.y = h01;
                __nv_bfloat162 ph1; ph1.x = h10; ph1.y = h11;
                __nv_bfloat162 pl0;
                pl0.x = __float2bfloat16(c00 - __bfloat162float(h00));
                pl0.y = __float2bfloat16(c01 - __bfloat162float(h01));
                __nv_bfloat162 pl1;
                pl1.x = __float2bfloat16(c10 - __bfloat162float(h10));
                pl1.y = __float2bfloat16(c11 - __bfloat162float(h11));
                *(__nv_bfloat162*)(Ch + (size_t)r0 * Nfull + col) = ph0;
                *(__nv_bfloat162*)(Ch + (size_t)r1 * Nfull + col) = ph1;
                *(__nv_bfloat162*)(Cl + (size_t)r0 * Nfull + col) = pl0;
                *(__nv_bfloat162*)(Cl + (size_t)r1 * Nfull + col) = pl1;
            } else {
                const float2 x0 = *(const float2*)(Xres + (size_t)r0 * 512 + col);
                const float2 x1 = *(const float2*)(Xres + (size_t)r1 * 512 + col);
                *(float2*)(Cf + (size_t)r0 * Nfull + col) =
                    make_float2(c00 + x0.x, c01 + x0.y);
                *(float2*)(Cf + (size_t)r1 * Nfull + col) =
                    make_float2(c10 + x1.x, c11 + x1.y);
            }
        }
    }
}

// ---------------------------------------------------------------------------
// pre-pass: elementwise fp32 -> bf16 hi/lo split (float4 granularity)
// ---------------------------------------------------------------------------
__global__ void split_kernel(const float* __restrict__ s,
                             __nv_bfloat16* __restrict__ h,
                             __nv_bfloat16* __restrict__ l, int n4)
{
    int i = blockIdx.x * blockDim.x + threadIdx.x;
    if (i >= n4) return;
    const float4 v = ((const float4*)s)[i];
    float a[4] = {v.x, v.y, v.z, v.w};
    __nv_bfloat16 hh[4], ll[4];
#pragma unroll
    for (int j = 0; j < 4; j++) {
        hh[j] = __float2bfloat16(a[j]);
        ll[j] = __float2bfloat16(a[j] - __bfloat162float(hh[j]));
    }
    __nv_bfloat162 p0; p0.x = hh[0]; p0.y = hh[1];
    __nv_bfloat162 p1; p1.x = hh[2]; p1.y = hh[3];
    __nv_bfloat162 q0; q0.x = ll[0]; q0.y = ll[1];
    __nv_bfloat162 q1; q1.x = ll[2]; q1.y = ll[3];
    ((__nv_bfloat162*)h)[i*2]   = p0;
    ((__nv_bfloat162*)h)[i*2+1] = p1;
    ((__nv_bfloat162*)l)[i*2]   = q0;
    ((__nv_bfloat162*)l)[i*2+1] = q1;
}

// pre-pass: W [K][N] fp32 -> Wh/Wl [N][K] bf16 (transpose + split)
__global__ void wsplit_kernel(const float* __restrict__ W,
                              __nv_bfloat16* __restrict__ Wh,
                              __nv_bfloat16* __restrict__ Wl, int K, int N)
{
    __shared__ float s[32][33];
    const int k0 = blockIdx.y * 32, n0 = blockIdx.x * 32;
    const int tx = threadIdx.x, ty = threadIdx.y;   // 32 x 8
#pragma unroll
    for (int i = 0; i < 4; i++)
        s[ty + 8*i][tx] = W[(size_t)(k0 + ty + 8*i) * N + n0 + tx];
    __syncthreads();
#pragma unroll
    for (int i = 0; i < 4; i++) {
        const float v = s[tx][ty + 8*i];
        const __nv_bfloat16 h = __float2bfloat16(v);
        const __nv_bfloat16 l = __float2bfloat16(v - __bfloat162float(h));
        const size_t o = (size_t)(n0 + ty + 8*i) * K + k0 + tx;
        Wh[o] = h;
        Wl[o] = l;
    }
}

// ---------------------------------------------------------------------------
// routing kernels (SIMT fp32 — small fraction of runtime)
// ---------------------------------------------------------------------------
__global__ __launch_bounds__(256) void aff_kernel(
    const float* __restrict__ q, const float* __restrict__ cores,
    float* __restrict__ aff)
{
    const int bh = blockIdx.y;
    const int b = bh >> 3, h = bh & 7;
    const int p0 = blockIdx.x * 64;
    __shared__ float cs[64][64];
    __shared__ float qs[64][65];
    const int tid = threadIdx.x;
    for (int idx = tid; idx < 4096; idx += 256) {
        int c = idx >> 6, d = idx & 63;
        cs[c][d] = cores[((size_t)h*64 + c)*64 + d];
    }
    for (int idx = tid; idx < 4096; idx += 256) {
        int p = idx >> 6, d = idx & 63;
        qs[p][d] = q[((size_t)(b*PP + p0 + p))*DD + h*64 + d];
    }
    __syncthreads();
    const int tp = tid & 31;
    const int tc = tid >> 5;
    float acc[2][8];
#pragma unroll
    for (int pp = 0; pp < 2; pp++)
#pragma unroll
        for (int cc = 0; cc < 8; cc++) acc[pp][cc] = 0.0f;
    for (int d = 0; d < 64; d++) {
        float qv0 = qs[tp][d];
        float qv1 = qs[tp + 32][d];
        float cv[8];
#pragma unroll
        for (int cc = 0; cc < 8; cc++) cv[cc] = cs[tc + 8*cc][d];
#pragma unroll
        for (int cc = 0; cc < 8; cc++) {
            acc[0][cc] += qv0 * cv[cc];
            acc[1][cc] += qv1 * cv[cc];
        }
    }
#pragma unroll
    for (int pp = 0; pp < 2; pp++)
#pragma unroll
        for (int cc = 0; cc < 8; cc++)
            aff[((size_t)bh*64 + tc + 8*cc)*PP + p0 + tp + 32*pp] = acc[pp][cc] * 0.125f;
}

__global__ __launch_bounds__(256) void softmax_p_kernel(
    const float* __restrict__ aff, float* __restrict__ out)
{
    const int row = blockIdx.x;
    const float* a = aff + (size_t)row * PP;
    const int tid = threadIdx.x;
    __shared__ float sm[256];
    float v[8];
    float m = -1e30f;
#pragma unroll
    for (int i = 0; i < 8; i++) { v[i] = a[tid + 256*i]; m = fmaxf(m, v[i]); }
    sm[tid] = m; __syncthreads();
    for (int s = 128; s > 0; s >>= 1) {
        if (tid < s) sm[tid] = fmaxf(sm[tid], sm[tid + s]);
        __syncthreads();
    }
    m = sm[0];
    __syncthreads();
    float s = 0.0f;
#pragma unroll
    for (int i = 0; i < 8; i++) { v[i] = expf(v[i] - m); s += v[i]; }
    sm[tid] = s; __syncthreads();
    for (int s2 = 128; s2 > 0; s2 >>= 1) {
        if (tid < s2) sm[tid] += sm[tid + s2];
        __syncthreads();
    }
    const float inv = 1.0f / sm[0];
    float* o = out + (size_t)row * PP;
#pragma unroll
    for (int i = 0; i < 8; i++) o[tid + 256*i] = v[i] * inv;
}

__global__ __launch_bounds__(256) void softmax_c_kernel(
    const float* __restrict__ aff, float* __restrict__ out)
{
    const int bh = blockIdx.x;
    const int p0 = blockIdx.y * 64;
    __shared__ float t[64][65];
    __shared__ float red[4][64];
    const int tid = threadIdx.x;
    for (int idx = tid; idx < 4096; idx += 256) {
        int c = idx >> 6, p = idx & 63;
        t[c][p] = aff[((size_t)bh*64 + c)*PP + p0 + p];
    }
    __syncthreads();
    const int p = tid & 63;
    const int g = tid >> 6;
    float m = -1e30f;
    for (int c = g*16; c < g*16 + 16; c++) m = fmaxf(m, t[c][p]);
    red[g][p] = m; __syncthreads();
    const float mm = fmaxf(fmaxf(red[0][p], red[1][p]), fmaxf(red[2][p], red[3][p]));
    __syncthreads();
    float s = 0.0f;
    for (int c = g*16; c < g*16 + 16; c++) {
        const float e = expf(t[c][p] - mm);
        t[c][p] = e;
        s += e;
    }
    red[g][p] = s; __syncthreads();
    const float ss = red[0][p] + red[1][p] + red[2][p] + red[3][p];
    const float inv = 1.0f / ss;
    for (int c = g*16; c < g*16 + 16; c++)
        out[((size_t)bh*64 + c)*PP + p0 + p] = t[c][p] * inv;
}

__global__ __launch_bounds__(256) void vcore_kernel(
    const float* __restrict__ x, const float* __restrict__ ac2p,
    float* __restrict__ vcore)
{
    const int bh = blockIdx.x;
    const int b = bh >> 3, h = bh & 7;
    __shared__ float a_s[64][64];
    __shared__ float v_s[64][64];
    const int tid = threadIdx.x;
    const int tj = tid & 15;
    const int ti = tid >> 4;
    float acc[4][4];
#pragma unroll
    for (int i = 0; i < 4; i++)
#pragma unroll
        for (int j = 0; j < 4; j++) acc[i][j] = 0.0f;
    for (int p0 = 0; p0 < PP; p0 += 64) {
        for (int idx = tid; idx < 4096; idx += 256) {
            int c = idx >> 6, p = idx & 63;
            a_s[c][p] = ac2p[((size_t)bh*64 + c)*PP + p0 + p];
        }
        for (int idx = tid; idx < 4096; idx += 256) {
            int p = idx >> 6, d = idx & 63;
            v_s[p][d] = x[((size_t)(b*PP + p0 + p))*DD + h*64 + d];
        }
        __syncthreads();
        for (int p = 0; p < 64; p++) {
            float av[4], vv[4];
#pragma unroll
            for (int i = 0; i < 4; i++) av[i] = a_s[ti + 16*i][p];
#pragma unroll
            for (int j = 0; j < 4; j++) vv[j] = v_s[p][tj + 16*j];
#pragma unroll
            for (int i = 0; i < 4; i++)
#pragma unroll
                for (int j = 0; j < 4; j++) acc[i][j] += av[i] * vv[j];
        }
        __syncthreads();
    }
#pragma unroll
    for (int i = 0; i < 4; i++)
#pragma unroll
        for (int j = 0; j < 4; j++)
            vcore[((size_t)bh*64 + ti + 16*i)*64 + tj + 16*j] = acc[i][j];
}

// FUSED: v_patch + ffn-input concat + bf16 hi/lo split.
__global__ __launch_bounds__(256) void vpatch_ffnin_kernel(
    const float* __restrict__ vcore, const float* __restrict__ ap2c,
    const float* __restrict__ X,
    __nv_bfloat16* __restrict__ fh, __nv_bfloat16* __restrict__ fl)
{
    const int bh = blockIdx.x;
    const int b = bh >> 3, h = bh & 7;
    const int p0 = blockIdx.y * 64;
    __shared__ float vc[64][64];
    __shared__ float a_s[64][64];
    const int tid = threadIdx.x;
    for (int idx = tid; idx < 4096; idx += 256) {
        int c = idx >> 6, d = idx & 63;
        vc[c][d] = vcore[((size_t)bh*64 + c)*64 + d];
    }
    for (int idx = tid; idx < 4096; idx += 256) {
        int c = idx >> 6, p = idx & 63;
        a_s[c][p] = ap2c[((size_t)bh*64 + c)*PP + p0 + p];
    }
    __syncthreads();
    const int tj = tid & 15;
    const int ti = tid >> 4;
    float acc[4][4];
#pragma unroll
    for (int i = 0; i < 4; i++)
#pragma unroll
        for (int j = 0; j < 4; j++) acc[i][j] = 0.0f;
    for (int c = 0; c < 64; c++) {
        float av[4], vv[4];
#pragma unroll
        for (int i = 0; i < 4; i++) av[i] = a_s[c][ti + 16*i];
#pragma unroll
        for (int j = 0; j < 4; j++) vv[j] = vc[c][tj + 16*j];
#pragma unroll
        for (int i = 0; i < 4; i++)
#pragma unroll
            for (int j = 0; j < 4; j++) acc[i][j] += av[i] * vv[j];
    }
#pragma unroll
    for (int i = 0; i < 4; i++) {
        const size_t m = (size_t)(b*PP + p0 + ti + 16*i);
#pragma unroll
        for (int j = 0; j < 4; j++) {
            const int col = h*64 + tj + 16*j;
            const float v = acc[i][j];
            const float d1 = X[m*DD + col] - v;
            const __nv_bfloat16 h1 = __float2bfloat16(d1);
            fh[m*FFN_IN + col] = h1;
            fl[m*FFN_IN + col] = __float2bfloat16(d1 - __bfloat162float(h1));
            const __nv_bfloat16 h2 = __float2bfloat16(v);
            fh[m*FFN_IN + 512 + col] = h2;
            fl[m*FFN_IN + 512 + col] = __float2bfloat16(v - __bfloat162float(h2));
        }
    }
}

// LayerNorm over last dim (512). 256 threads/row; warp-shuffle reduction.
__global__ __launch_bounds__(256) void ln_kernel(
    const float* __restrict__ in, const float* __restrict__ gamma,
    const float* __restrict__ beta, float* __restrict__ out)
{
    const int row = blockIdx.x;
    const float* r = in + (size_t)row * DD;
    const int tid = threadIdx.x;
    const int wid = tid >> 5, lid = tid & 31;
    __shared__ float wsum[8], wsq[8];

    const float x0 = r[tid], x1 = r[tid + 256];
    float s  = x0 + x1;
    float sq = x0*x0 + x1*x1;
#pragma unroll
    for (int o = 16; o > 0; o >>= 1) {
        s  += __shfl_xor_sync(0xFFFFFFFFu, s,  o);
        sq += __shfl_xor_sync(0xFFFFFFFFu, sq, o);
    }
    if (lid == 0) { wsum[wid] = s; wsq[wid] = sq; }
    __syncthreads();
    float ts = wsum[lid & 7], tq = wsq[lid & 7];
#pragma unroll
    for (int o = 4; o > 0; o >>= 1) {
        ts += __shfl_xor_sync(0xFFFFFFFFu, ts, o);
        tq += __shfl_xor_sync(0xFFFFFFFFu, tq, o);
    }
    ts = __shfl_sync(0xFFFFFFFFu, ts, 0);
    tq = __shfl_sync(0xFFFFFFFFu, tq, 0);

    const float mu  = ts * (1.0f / 512.0f);
    const float var = tq * (1.0f / 512.0f) - mu*mu;
    const float inv = rsqrtf(var + 1e-5f);

    float* o = out + (size_t)row * DD;
    o[tid]       = (x0 - mu) * inv * gamma[tid]       + beta[tid];
    o[tid + 256] = (x1 - mu) * inv * gamma[tid + 256] + beta[tid + 256];
}

// ---------------------------------------------------------------------------
extern "C" void kernel_launch(void* const* d_in, const int* in_sizes, int n_in,
                              void* d_out, int out_size)
{
    const float* input = (const float*)d_in[0];
    const float* cores = (const float*)d_in[1];
    const float* Wv    = (const float*)d_in[2];
    const float* bv    = (const float*)d_in[3];
    const float* W1    = (const float*)d_in[4];
    const float* b1    = (const float*)d_in[5];
    const float* W2    = (const float*)d_in[6];
    const float* b2    = (const float*)d_in[7];
    const float* gamma = (const float*)d_in[8];
    const float* beta  = (const float*)d_in[9];
    float* out = (float*)d_out;

    float *q, *aff, *ac2p, *ap2c, *vcore, *ffnout;
    cudaGetSymbolAddress((void**)&q,      g_q);
    cudaGetSymbolAddress((void**)&aff,    g_aff);
    cudaGetSymbolAddress((void**)&ac2p,   g_ac2p);
    cudaGetSymbolAddress((void**)&ap2c,   g_ap2c);
    cudaGetSymbolAddress((void**)&vcore,  g_vcore);
    cudaGetSymbolAddress((void**)&ffnout, g_ffnout);
    __nv_bfloat16 *xh, *xl, *fh, *fl, *hh, *hl, *wvh, *wvl, *w1h, *w1l, *w2h, *w2l;
    cudaGetSymbolAddress((void**)&xh,  g_xh);
    cudaGetSymbolAddress((void**)&xl,  g_xl);
    cudaGetSymbolAddress((void**)&fh,  g_fh);
    cudaGetSymbolAddress((void**)&fl,  g_fl);
    cudaGetSymbolAddress((void**)&hh,  g_hidh);
    cudaGetSymbolAddress((void**)&hl,  g_hidl);
    cudaGetSymbolAddress((void**)&wvh, g_wvh);
    cudaGetSymbolAddress((void**)&wvl, g_wvl);
    cudaGetSymbolAddress((void**)&w1h, g_w1h);
    cudaGetSymbolAddress((void**)&w1l, g_w1l);
    cudaGetSymbolAddress((void**)&w2h, g_w2h);
    cudaGetSymbolAddress((void**)&w2l, g_w2l);

    cudaFuncSetAttribute(mma_gemm, cudaFuncAttributeMaxDynamicSharedMemorySize,
                         SMEM_BYTES);

    // --- pre-passes: operand splits ---
    split_kernel<<<(MM*DD/4 + 255)/256, 256>>>(input, xh, xl, MM*DD/4);
    wsplit_kernel<<<dim3(DD/32, DD/32), dim3(32,8)>>>(Wv, wvh, wvl, DD, DD);
    wsplit_kernel<<<dim3(FFN_HID/32, FFN_IN/32), dim3(32,8)>>>(W1, w1h, w1l, FFN_IN, FFN_HID);
    wsplit_kernel<<<dim3(DD/32, FFN_HID/32), dim3(32,8)>>>(W2, w2h, w2l, FFN_HID, DD);

    // --- 1) value projection: q = X @ Wv + bv (fp32 out) ---
    mma_gemm<<<dim3(DD/GBN, MM/GBM), 256, SMEM_BYTES>>>(
        xh, xl, wvh, wvl, bv, nullptr, q, nullptr, nullptr, DD, DD, 0);

    // --- 2-5) routing ---
    aff_kernel<<<dim3(PP/64, BB*HH), 256>>>(q, cores, aff);
    softmax_p_kernel<<<BB*HH*CC, 256>>>(aff, ac2p);
    softmax_c_kernel<<<dim3(BB*HH, PP/64), 256>>>(aff, ap2c);
    vcore_kernel<<<BB*HH, 256>>>(input, ac2p, vcore);

    // --- 6) fused v_patch + FFN-input concat/split ---
    vpatch_ffnin_kernel<<<dim3(BB*HH, PP/64), 256>>>(vcore, ap2c, input, fh, fl);

    // --- 7) FFN layer 1 + exact GELU -> hid (bf16 split) ---
    mma_gemm<<<dim3(FFN_HID/GBN, MM/GBM), 256, SMEM_BYTES>>>(
        fh, fl, w1h, w1l, b1, nullptr, nullptr, hh, hl, FFN_IN, FFN_HID, 1);

    // --- 8) FFN layer 2 + residual -> ffnout (fp32) ---
    mma_gemm<<<dim3(DD/GBN, MM/GBM), 256, SMEM_BYTES>>>(
        hh, hl, w2h, w2l, b2, input, ffnout, nullptr, nullptr, FFN_HID, DD, 2);

    // --- 9) LayerNorm -> output ---
    ln_kernel<<<MM, 256>>>(ffnout, gamma, beta, out);
}